// round 4
// baseline (speedup 1.0000x reference)
#include <cuda_runtime.h>
#include <cstdint>

// RRSVM rank-weighted pooling, 3x3 window, stride 2, pad 1.
// x: [32, 64, 112, 112] f32   s: [64, 3, 3] f32
// d_out (f32, concatenated): out [32,64,56,56], order [32,64,56,56,9]

#define BB 32
#define CC 64
#define HH 112
#define WW 112
#define HO 56
#define WO 56
#define PIX_PER_CH (HO * WO)      // 3136
#define NQ (BB * CC)              // 2048
#define TPB 256

__global__ void __launch_bounds__(TPB, 4) rrsvm_kernel(
        const float* __restrict__ x,
        const float* __restrict__ s,
        float* __restrict__ out,
        float* __restrict__ order,
        int write_order) {
    __shared__ __align__(16) float ord_sh[TPB * 9];  // order staging (16B for float4)
    __shared__ float s_sh[18];          // s rows for the (<=2) channels this block touches

    const int tid = threadIdx.x;
    const unsigned p0 = blockIdx.x * TPB;
    const unsigned p = p0 + tid;

    const int q_first = (int)(p0 / PIX_PER_CH);
    const int q = (int)(p / PIX_PER_CH);

    // Load the 1-2 needed s rows (9 floats each) into shared.
    if (tid < 18) {
        int qq = q_first + tid / 9;
        if (qq < NQ) s_sh[tid] = s[(qq & (CC - 1)) * 9 + (tid % 9)];
    }
    __syncthreads();

    const int cbase = (q - q_first) * 9;   // 0 or 9
    const int pix = (int)(p % PIX_PER_CH);
    const int wo = pix % WO;
    const int ho = pix / WO;

    const float* xp = x + (unsigned)q * (HH * WW);
    const int h0 = 2 * ho - 1;
    const int w0 = 2 * wo - 1;

    float v[9];
    #pragma unroll
    for (int i = 0; i < 3; i++) {
        int h = h0 + i;
        bool hv = ((unsigned)h < (unsigned)HH);
        const float* row = xp + h * WW;
        #pragma unroll
        for (int j = 0; j < 3; j++) {
            int w = w0 + j;
            v[i * 3 + j] = (hv && (unsigned)w < (unsigned)WW) ? __ldg(row + w) : 0.0f;
        }
    }

    // Pairwise masks via FSET: m[i][j] = (v[j] > v[i]) ? -1 : 0.
    // Strict-greater only => ties keep index order (stable argsort of -v).
    int m[9][9];
    #pragma unroll
    for (int i = 0; i < 8; i++) {
        #pragma unroll
        for (int j = i + 1; j < 9; j++) {
            asm("set.gt.s32.f32 %0, %1, %2;"
                : "=r"(m[i][j]) : "f"(v[j]), "f"(v[i]));
        }
    }

    // rank_k = k - sum_{j>k} m[k][j] + sum_{i<k} m[i][k]
    // (IADD3-foldable mask sums)
    int r[9];
    #pragma unroll
    for (int k = 0; k < 9; k++) {
        int acc = k;
        #pragma unroll
        for (int j = k + 1; j < 9; j++) acc -= m[k][j];
        #pragma unroll
        for (int i = 0; i < k; i++)     acc += m[i][k];
        r[k] = acc;
    }

    // Weighted sum: out = sum_k v[k] * s[rank_k]
    float sum = 0.0f;
    #pragma unroll
    for (int k = 0; k < 9; k++) {
        sum += v[k] * s_sh[cbase + r[k]];
    }
    out[p] = sum;

    if (write_order) {
        // Scatter order indices: segment[rank_k] = k  (as float).
        float* my = ord_sh + tid * 9;
        #pragma unroll
        for (int k = 0; k < 9; k++) {
            my[r[k]] = (float)k;
        }
        __syncwarp();
        // Warp-coalesced vectorized copy-out: 288 floats = 72 float4 per warp.
        const int w = tid >> 5;
        const int lane = tid & 31;
        const float4* src = (const float4*)(ord_sh + w * 288);
        float4* dst = (float4*)(order + (p0 + (unsigned)w * 32) * 9);
        dst[lane]      = src[lane];
        dst[lane + 32] = src[lane + 32];
        if (lane < 8) dst[lane + 64] = src[lane + 64];
    }
}

extern "C" void kernel_launch(void* const* d_in, const int* in_sizes, int n_in,
                              void* d_out, int out_size) {
    const float* x = (const float*)d_in[0];
    const float* s = (const float*)d_in[1];
    const long long NPIX = (long long)BB * CC * HO * WO;  // 6,422,528

    float* out = (float*)d_out;
    float* order = out + NPIX;
    int write_order = ((long long)out_size >= NPIX * 10LL) ? 1 : 0;

    const long long blocks = (NPIX + TPB - 1) / TPB;  // 25088, exact
    rrsvm_kernel<<<(unsigned)blocks, TPB>>>(x, s, out, order, write_order);
}

// round 5
// speedup vs baseline: 1.1902x; 1.1902x over previous
#include <cuda_runtime.h>
#include <cstdint>

// RRSVM rank-weighted pooling, 3x3 window, stride 2, pad 1.
// x: [32, 64, 112, 112] f32   s: [64, 3, 3] f32
// d_out (f32, concatenated): out [32,64,56,56], order [32,64,56,56,9]

#define BB 32
#define CC 64
#define HH 112
#define WW 112
#define HO 56
#define WO 56
#define PIX_PER_CH (HO * WO)      // 3136
#define NQ (BB * CC)              // 2048
#define TPB 256

__global__ void __launch_bounds__(TPB, 8) rrsvm_kernel(
        const float* __restrict__ x,
        const float* __restrict__ s,
        float* __restrict__ out,
        float* __restrict__ order,
        int write_order) {
    __shared__ __align__(16) float ord_sh[TPB * 9];  // order staging (16B for float4)
    __shared__ float s_sh[18];          // s rows for the (<=2) channels this block touches

    const int tid = threadIdx.x;
    const unsigned p0 = blockIdx.x * TPB;
    const unsigned p = p0 + tid;

    const int q_first = (int)(p0 / PIX_PER_CH);
    const int q = (int)(p / PIX_PER_CH);

    // Load the 1-2 needed s rows (9 floats each) into shared.
    if (tid < 18) {
        int qq = q_first + tid / 9;
        if (qq < NQ) s_sh[tid] = s[(qq & (CC - 1)) * 9 + (tid % 9)];
    }
    __syncthreads();

    const int cbase = (q - q_first) * 9;   // 0 or 9
    const int pix = (int)(p % PIX_PER_CH);
    const int wo = pix % WO;
    const int ho = pix / WO;

    const float* xp = x + (unsigned)q * (HH * WW);
    const int h0 = 2 * ho - 1;
    const int w0 = 2 * wo - 1;

    float v[9];
    #pragma unroll
    for (int i = 0; i < 3; i++) {
        int h = h0 + i;
        bool hv = ((unsigned)h < (unsigned)HH);
        const float* row = xp + h * WW;
        #pragma unroll
        for (int j = 0; j < 3; j++) {
            int w = w0 + j;
            v[i * 3 + j] = (hv && (unsigned)w < (unsigned)WW) ? __ldg(row + w) : 0.0f;
        }
    }

    // Pairwise ranks via FSET masks consumed immediately (no mask array ->
    // no register blowup). m = (v[j] > v[i]) ? -1 : 0.  Strict-greater only
    // => ties keep index order (stable argsort of -v).
    int r[9];
    #pragma unroll
    for (int k = 0; k < 9; k++) r[k] = k;
    #pragma unroll
    for (int i = 0; i < 8; i++) {
        #pragma unroll
        for (int j = i + 1; j < 9; j++) {
            int m;
            asm("set.gt.s32.f32 %0, %1, %2;"
                : "=r"(m) : "f"(v[j]), "f"(v[i]));
            r[i] -= m;   // v[j] wins: i ranks one later
            r[j] += m;   // j ranks one earlier
        }
    }

    // Weighted sum: out = sum_k v[k] * s[rank_k]
    float sum = 0.0f;
    #pragma unroll
    for (int k = 0; k < 9; k++) {
        sum += v[k] * s_sh[cbase + r[k]];
    }
    out[p] = sum;

    if (write_order) {
        // Scatter order indices: segment[rank_k] = k  (as float).
        float* my = ord_sh + tid * 9;
        #pragma unroll
        for (int k = 0; k < 9; k++) {
            my[r[k]] = (float)k;
        }
        __syncwarp();
        // Warp-coalesced vectorized copy-out: 288 floats = 72 float4 per warp.
        const int w = tid >> 5;
        const int lane = tid & 31;
        const float4* src = (const float4*)(ord_sh + w * 288);
        float4* dst = (float4*)(order + (p0 + (unsigned)w * 32) * 9);
        dst[lane]      = src[lane];
        dst[lane + 32] = src[lane + 32];
        if (lane < 8) dst[lane + 64] = src[lane + 64];
    }
}

extern "C" void kernel_launch(void* const* d_in, const int* in_sizes, int n_in,
                              void* d_out, int out_size) {
    const float* x = (const float*)d_in[0];
    const float* s = (const float*)d_in[1];
    const long long NPIX = (long long)BB * CC * HO * WO;  // 6,422,528

    float* out = (float*)d_out;
    float* order = out + NPIX;
    int write_order = ((long long)out_size >= NPIX * 10LL) ? 1 : 0;

    const long long blocks = (NPIX + TPB - 1) / TPB;  // 25088, exact
    rrsvm_kernel<<<(unsigned)blocks, TPB>>>(x, s, out, order, write_order);
}

// round 6
// speedup vs baseline: 1.3244x; 1.1127x over previous
#include <cuda_runtime.h>
#include <cstdint>

// RRSVM rank-weighted pooling, 3x3 window, stride 2, pad 1.
// x: [32, 64, 112, 112] f32   s: [64, 3, 3] f32
// d_out (f32, concatenated): out [32,64,56,56], order [32,64,56,56,9]

#define BB 32
#define CC 64
#define HH 112
#define WW 112
#define HO 56
#define WO 56
#define PIX_PER_CH (HO * WO)      // 3136
#define NQ (BB * CC)              // 2048
#define TPB 256

__global__ void __launch_bounds__(TPB, 8) rrsvm_kernel(
        const float* __restrict__ x,
        const float* __restrict__ s,
        float* __restrict__ out,
        float* __restrict__ order,
        int write_order) {
    __shared__ __align__(16) float ord_sh[TPB * 9];  // order staging (16B for float4)
    __shared__ float s_sh[18];          // s rows for the (<=2) channels this block touches

    const int tid = threadIdx.x;
    const unsigned p0 = blockIdx.x * TPB;
    const unsigned p = p0 + tid;

    const int q_first = (int)(p0 / PIX_PER_CH);
    const int q = (int)(p / PIX_PER_CH);

    // Load the 1-2 needed s rows (9 floats each) into shared.
    if (tid < 18) {
        int qq = q_first + tid / 9;
        if (qq < NQ) s_sh[tid] = s[(qq & (CC - 1)) * 9 + (tid % 9)];
    }
    __syncthreads();

    const int cbase = (q - q_first) * 9;   // 0 or 9
    const int pix = (int)(p % PIX_PER_CH);
    const int wo = pix % WO;
    const int ho = pix / WO;

    const float* xp = x + (unsigned)q * (HH * WW);
    const bool wv = (wo > 0);            // col 2wo-1 in range?

    // Window rows: h = 2ho-1+i. Only i=0 can be out of range (ho==0).
    // Window cols: 2wo-1 (guarded), 2wo & 2wo+1 (always valid, 8B-aligned
    // pair -> dense float2 load).
    float v[9];
    #pragma unroll
    for (int i = 0; i < 3; i++) {
        const int h = 2 * ho - 1 + i;
        const bool hv = (i == 0) ? (ho > 0) : true;
        const float* row = xp + h * WW;
        v[i * 3] = (hv && wv) ? __ldg(row + 2 * wo - 1) : 0.0f;
        float2 bc = make_float2(0.0f, 0.0f);
        if (hv) bc = *(const float2*)(row + 2 * wo);
        v[i * 3 + 1] = bc.x;
        v[i * 3 + 2] = bc.y;
    }

    // Pairwise ranks on the FMA pipe: FSET produces a 1.0f/0.0f mask,
    // accumulated with FADD. Strict-greater only => ties keep index order
    // (stable argsort of -v). Sums are small exact integers in f32.
    float rf[9];
    #pragma unroll
    for (int k = 0; k < 9; k++) rf[k] = (float)k;
    #pragma unroll
    for (int i = 0; i < 8; i++) {
        #pragma unroll
        for (int j = i + 1; j < 9; j++) {
            float m;
            asm("set.gt.f32.f32 %0, %1, %2;"
                : "=f"(m) : "f"(v[j]), "f"(v[i]));
            rf[i] += m;   // v[j] wins: i ranks one later
            rf[j] -= m;   // j ranks one earlier
        }
    }
    int r[9];
    #pragma unroll
    for (int k = 0; k < 9; k++) r[k] = (int)rf[k];

    // Weighted sum: out = sum_k v[k] * s[rank_k]
    float sum = 0.0f;
    #pragma unroll
    for (int k = 0; k < 9; k++) {
        sum += v[k] * s_sh[cbase + r[k]];
    }
    out[p] = sum;

    if (write_order) {
        // Scatter order indices: segment[rank_k] = k  (as float).
        float* my = ord_sh + tid * 9;
        #pragma unroll
        for (int k = 0; k < 9; k++) {
            my[r[k]] = (float)k;
        }
        __syncwarp();
        // Warp-coalesced vectorized copy-out: 288 floats = 72 float4 per warp.
        const int w = tid >> 5;
        const int lane = tid & 31;
        const float4* src = (const float4*)(ord_sh + w * 288);
        float4* dst = (float4*)(order + (p0 + (unsigned)w * 32) * 9);
        dst[lane]      = src[lane];
        dst[lane + 32] = src[lane + 32];
        if (lane < 8) dst[lane + 64] = src[lane + 64];
    }
}

extern "C" void kernel_launch(void* const* d_in, const int* in_sizes, int n_in,
                              void* d_out, int out_size) {
    const float* x = (const float*)d_in[0];
    const float* s = (const float*)d_in[1];
    const long long NPIX = (long long)BB * CC * HO * WO;  // 6,422,528

    float* out = (float*)d_out;
    float* order = out + NPIX;
    int write_order = ((long long)out_size >= NPIX * 10LL) ? 1 : 0;

    const long long blocks = (NPIX + TPB - 1) / TPB;  // 25088, exact
    rrsvm_kernel<<<(unsigned)blocks, TPB>>>(x, s, out, order, write_order);
}